// round 6
// baseline (speedup 1.0000x reference)
#include <cuda_runtime.h>
#include <cuda_bf16.h>
#include <cstdint>

#define HN   128
#define MAXN 100000
#define MAXE 1600000
#define MAXS 10000
#define TM   32
#define WS   136            // padded bf16 plane stride: ldsm rows conflict-free
#define PLANE (HN * WS)     // 17408
#define TMWS  (TM * WS)     // 4352

// ---------------- scratch (static device globals; no allocation) ----------------
__device__ float g_bufA[(size_t)MAXN * HN];
__device__ float g_bufB[(size_t)MAXN * HN];
__device__ float g_agg0[MAXN];
__device__ int   g_ei[2 * MAXE];
__device__ int   g_sub[MAXN];
__device__ int   g_s2g[MAXS];
__device__ int   g_comp[MAXN];
__device__ int   g_deg[MAXN];
__device__ int   g_offs[MAXN + 1];
__device__ int   g_cursor[MAXN];
__device__ int   g_csr[MAXE];
__device__ int   g_is64;
__device__ __align__(16) __nv_bfloat16 g_wsplit[5 * 2 * PLANE];

// ---------------- helpers ----------------
__device__ __forceinline__ uint32_t sptr(const void* p) {
    return (uint32_t)__cvta_generic_to_shared(p);
}
__device__ __forceinline__ void splitf(float x, __nv_bfloat16& h, __nv_bfloat16& l) {
    h = __float2bfloat16(x);
    l = __float2bfloat16(x - __bfloat162float(h));
}
__device__ __forceinline__ void ldsm4(uint32_t a, uint32_t& r0, uint32_t& r1,
                                      uint32_t& r2, uint32_t& r3) {
    asm volatile("ldmatrix.sync.aligned.m8n8.x4.shared.b16 {%0,%1,%2,%3},[%4];"
                 : "=r"(r0), "=r"(r1), "=r"(r2), "=r"(r3) : "r"(a));
}
__device__ __forceinline__ void ldsm4t(uint32_t a, uint32_t& r0, uint32_t& r1,
                                       uint32_t& r2, uint32_t& r3) {
    asm volatile("ldmatrix.sync.aligned.m8n8.x4.trans.shared.b16 {%0,%1,%2,%3},[%4];"
                 : "=r"(r0), "=r"(r1), "=r"(r2), "=r"(r3) : "r"(a));
}
__device__ __forceinline__ void mma16816(float* c, uint32_t a0, uint32_t a1, uint32_t a2,
                                         uint32_t a3, uint32_t b0, uint32_t b1) {
    asm volatile(
        "mma.sync.aligned.m16n8k16.row.col.f32.bf16.bf16.f32 "
        "{%0,%1,%2,%3},{%4,%5,%6,%7},{%8,%9},{%0,%1,%2,%3};"
        : "+f"(c[0]), "+f"(c[1]), "+f"(c[2]), "+f"(c[3])
        : "r"(a0), "r"(a1), "r"(a2), "r"(a3), "r"(b0), "r"(b1));
}

// ---------------- index dtype detection + normalization ----------------
__global__ void k_detect(const unsigned long long* __restrict__ p) {
    if (blockIdx.x == 0 && threadIdx.x == 0) {
        int is64 = 1;
        for (int i = 0; i < 64; i++)
            if (p[i] >> 32) { is64 = 0; break; }
        g_is64 = is64;
    }
}
__global__ void k_convert(const void* __restrict__ in, int* __restrict__ out, int n) {
    int i = blockIdx.x * blockDim.x + threadIdx.x;
    if (i >= n) return;
    if (g_is64) out[i] = (int)(((const long long*)in)[i]);
    else        out[i] = ((const int*)in)[i];
}

// ---------------- utility ----------------
__global__ void k_zero4(float* __restrict__ p, int n4) {
    int i = blockIdx.x * blockDim.x + threadIdx.x;
    if (i < n4) ((float4*)p)[i] = make_float4(0.f, 0.f, 0.f, 0.f);
}
__global__ void k_zeroi(int* __restrict__ p, int n) {
    int i = blockIdx.x * blockDim.x + threadIdx.x;
    if (i < n) p[i] = 0;
}

// ---------------- W split ----------------
__global__ void k_splitW(const float* __restrict__ W, __nv_bfloat16* __restrict__ dh,
                         __nv_bfloat16* __restrict__ dl) {
    int i = blockIdx.x * blockDim.x + threadIdx.x;
    if (i >= HN * HN) return;
    int k = i >> 7, n = i & 127;
    __nv_bfloat16 h, l;
    splitf(W[i], h, l);
    dh[k * WS + n] = h;
    dl[k * WS + n] = l;
}

// ---------------- CSR build ----------------
__global__ void k_hist(const int* __restrict__ dst, int* __restrict__ deg, int E) {
    int e = blockIdx.x * blockDim.x + threadIdx.x;
    if (e < E) atomicAdd(deg + dst[e], 1);
}
__global__ void k_scan(const int* __restrict__ deg, int* __restrict__ offs, int n) {
    __shared__ int sums[1024];
    int tid = threadIdx.x;
    int chunk = (n + 1023) / 1024;
    int start = tid * chunk;
    int end   = start + chunk; if (end > n) end = n;
    int s = 0;
    for (int i = start; i < end; i++) s += deg[i];
    sums[tid] = s;
    __syncthreads();
    for (int off = 1; off < 1024; off <<= 1) {
        int v = 0;
        if (tid >= off) v = sums[tid - off];
        __syncthreads();
        if (tid >= off) sums[tid] += v;
        __syncthreads();
    }
    int run = (tid == 0) ? 0 : sums[tid - 1];
    for (int i = start; i < end; i++) { offs[i] = run; run += deg[i]; }
    if (end == n) offs[n] = run;
}
__global__ void k_scatter(const int* __restrict__ src, const int* __restrict__ dst,
                          const int* __restrict__ offs, int* __restrict__ cursor,
                          int* __restrict__ csr, int E) {
    int e = blockIdx.x * blockDim.x + threadIdx.x;
    if (e >= E) return;
    int d = dst[e];
    int p = atomicAdd(cursor + d, 1);
    csr[offs[d] + p] = src[e];
}

// ---------------- layer-1 scalar aggregation ----------------
__global__ void k_agg0(const int* __restrict__ offs, const int* __restrict__ csr,
                       const float* __restrict__ x, float* __restrict__ agg, int N) {
    int warp = (blockIdx.x * blockDim.x + threadIdx.x) >> 5;
    int lane = threadIdx.x & 31;
    if (warp >= N) return;
    int s = offs[warp], e = offs[warp + 1];
    float acc = 0.f;
    for (int i = s + lane; i < e; i += 32) acc += __ldg(x + csr[i]);
#pragma unroll
    for (int o = 16; o; o >>= 1) acc += __shfl_xor_sync(0xffffffffu, acc, o);
    if (lane == 0) agg[warp] = acc + x[warp];
}

// ---------------- MMA: acc[4][4] = A[32,128] @ B[128,128] (split bf16, warp m16 x n32) ----------------
__device__ __forceinline__ void mma_tile(
    const __nv_bfloat16* Ah, const __nv_bfloat16* Al,
    const __nv_bfloat16* Bh, const __nv_bfloat16* Bl,
    int mrow0, int nbase, int lane, float acc[4][4]) {
#pragma unroll
    for (int j = 0; j < 4; j++)
#pragma unroll
        for (int c = 0; c < 4; c++) acc[j][c] = 0.f;

    int aoff = (mrow0 + (lane & 15)) * WS + ((lane >> 4) << 3);
    int brow = (lane & 15) * WS;
    int bn   = (lane >> 4) << 3;

#pragma unroll
    for (int kt = 0; kt < 8; kt++) {
        uint32_t ah0, ah1, ah2, ah3, al0, al1, al2, al3;
        ldsm4(sptr(Ah + aoff + kt * 16), ah0, ah1, ah2, ah3);
        ldsm4(sptr(Al + aoff + kt * 16), al0, al1, al2, al3);
#pragma unroll
        for (int jj = 0; jj < 2; jj++) {
            int nj = nbase + jj * 16;
            uint32_t bh0, bh1, bh2, bh3, bl0, bl1, bl2, bl3;
            ldsm4t(sptr(Bh + kt * 16 * WS + brow + nj + bn), bh0, bh1, bh2, bh3);
            ldsm4t(sptr(Bl + kt * 16 * WS + brow + nj + bn), bl0, bl1, bl2, bl3);
            mma16816(acc[2 * jj],     ah0, ah1, ah2, ah3, bh0, bh1);
            mma16816(acc[2 * jj],     ah0, ah1, ah2, ah3, bl0, bl1);
            mma16816(acc[2 * jj],     al0, al1, al2, al3, bh0, bh1);
            mma16816(acc[2 * jj + 1], ah0, ah1, ah2, ah3, bh2, bh3);
            mma16816(acc[2 * jj + 1], ah0, ah1, ah2, ah3, bl2, bl3);
            mma16816(acc[2 * jj + 1], al0, al1, al2, al3, bh2, bh3);
        }
    }
}

// ---------------- producer: gather+sum 8 rows into bf16 hi/lo A planes ----------------
__device__ __forceinline__ void gather_tile(
    const float* __restrict__ H, const int* __restrict__ offs, const int* __restrict__ csr,
    __nv_bfloat16* sAh, __nv_bfloat16* sAl,
    int row0, int nrows, int pw, int lane) {
#pragma unroll 1
    for (int lr = pw * 8; lr < pw * 8 + 8; lr++) {
        int gr = row0 + lr;
        float4 acc = make_float4(0.f, 0.f, 0.f, 0.f);
        if (gr < nrows) {
            acc = __ldg(((const float4*)(H + (size_t)gr * HN)) + lane);   // self
            int s = __ldg(offs + gr), e = __ldg(offs + gr + 1);
            int i = s;
#pragma unroll 1
            for (; i + 8 <= e; i += 8) {
                int idx[8];
#pragma unroll
                for (int u = 0; u < 8; u++) idx[u] = __ldg(csr + i + u);
                float4 v[8];
#pragma unroll
                for (int u = 0; u < 8; u++)
                    v[u] = __ldg(((const float4*)(H + (size_t)idx[u] * HN)) + lane);
#pragma unroll
                for (int u = 0; u < 8; u++) {
                    acc.x += v[u].x; acc.y += v[u].y; acc.z += v[u].z; acc.w += v[u].w;
                }
            }
            for (; i < e; i++) {
                float4 v = __ldg(((const float4*)(H + (size_t)__ldg(csr + i) * HN)) + lane);
                acc.x += v.x; acc.y += v.y; acc.z += v.z; acc.w += v.w;
            }
        }
        __nv_bfloat162 h01, h23, l01, l23;
        splitf(acc.x, h01.x, l01.x); splitf(acc.y, h01.y, l01.y);
        splitf(acc.z, h23.x, l23.x); splitf(acc.w, h23.y, l23.y);
        uint32_t* ah = (uint32_t*)(sAh + lr * WS + lane * 4);
        uint32_t* al = (uint32_t*)(sAl + lr * WS + lane * 4);
        ah[0] = *(uint32_t*)&h01; ah[1] = *(uint32_t*)&h23;
        al[0] = *(uint32_t*)&l01; al[1] = *(uint32_t*)&l23;
    }
}

// ---------------- fused GIN layer: gather (4 warps) || dual-MMA (8 warps) ----------------
// smem bf16: W1h W1l W2h W2l (PLANE each) | A[2 bufs][hi,lo] | Th Tl
#define OFF_A  (4 * PLANE)
#define OFF_T  (4 * PLANE + 4 * TMWS)
#define SMEM_ELEMS (4 * PLANE + 6 * TMWS)   // 95744 elems -> 191488 B

extern __shared__ __nv_bfloat16 sb[];

__global__ __launch_bounds__(384) void k_layer(
    const float* __restrict__ Hprev,
    const int* __restrict__ offs, const int* __restrict__ csr,
    const float* __restrict__ vscal, const float* __restrict__ W1v,
    const __nv_bfloat16* __restrict__ W1h, const __nv_bfloat16* __restrict__ W1l,
    const float* __restrict__ b1,
    const __nv_bfloat16* __restrict__ W2h, const __nv_bfloat16* __restrict__ W2l,
    const float* __restrict__ b2,
    float* __restrict__ Out, int nrows, int mode) {

    __shared__ float sv[TM];
    int tid  = threadIdx.x;
    int lane = tid & 31;
    int w    = tid >> 5;
    int mrow0 = (w >> 2) * 16;     // consumer row group (w<8)
    int nbase = (w & 3) * 32;      // consumer col group

    __nv_bfloat16* sW1h = sb;
    __nv_bfloat16* sW1l = sb + PLANE;
    __nv_bfloat16* sW2h = sb + 2 * PLANE;
    __nv_bfloat16* sW2l = sb + 3 * PLANE;
    __nv_bfloat16* sTh  = sb + OFF_T;
    __nv_bfloat16* sTl  = sb + OFF_T + TMWS;

    // load W planes once
    const int U4 = PLANE * 2 / 16;
    for (int i = tid; i < U4; i += 384) {
        ((uint4*)sW2h)[i] = ((const uint4*)W2h)[i];
        ((uint4*)sW2l)[i] = ((const uint4*)W2l)[i];
        if (mode == 1) {
            ((uint4*)sW1h)[i] = ((const uint4*)W1h)[i];
            ((uint4*)sW1l)[i] = ((const uint4*)W1l)[i];
        }
    }

    int ntiles = (nrows + TM - 1) / TM;

    if (mode == 0) {
        __syncthreads();
        for (int t = blockIdx.x; t < ntiles; t += gridDim.x) {
            int row0 = t * TM;
            int tr = nrows - row0; if (tr > TM) tr = TM;
            if (tid < TM) sv[tid] = (tid < tr) ? vscal[row0 + tid] : 0.f;
            __syncthreads();
            for (int i = tid; i < TM * HN; i += 384) {
                int r = i >> 7, c = i & 127;
                float v = fmaxf(fmaf(sv[r], __ldg(W1v + c), __ldg(b1 + c)), 0.f);
                __nv_bfloat16 h, l;
                splitf(v, h, l);
                sTh[r * WS + c] = h;
                sTl[r * WS + c] = l;
            }
            __syncthreads();
            if (w < 8) {
                float acc[4][4];
                mma_tile(sTh, sTl, sW2h, sW2l, mrow0, nbase, lane, acc);
                int r0 = mrow0 + (lane >> 2);
#pragma unroll
                for (int j = 0; j < 4; j++) {
                    int c = nbase + 8 * j + (lane & 3) * 2;
                    float bx = __ldg(b2 + c), by = __ldg(b2 + c + 1);
                    int gr0 = row0 + r0, gr1 = gr0 + 8;
                    if (gr0 < nrows)
                        *(float2*)(Out + (size_t)gr0 * HN + c) =
                            make_float2(fmaxf(acc[j][0] + bx, 0.f), fmaxf(acc[j][1] + by, 0.f));
                    if (gr1 < nrows)
                        *(float2*)(Out + (size_t)gr1 * HN + c) =
                            make_float2(fmaxf(acc[j][2] + bx, 0.f), fmaxf(acc[j][3] + by, 0.f));
                }
            }
            __syncthreads();
        }
        return;
    }

    // mode 1: pipelined producer/consumer
    int tp = blockIdx.x;   // tile being gathered this step
    int tc = -1;           // tile being computed this step (gathered last step)
    int par = 0;           // producer buffer parity
    for (;;) {
        bool doP = (tp < ntiles);
        bool doC = (tc >= 0);
        if (!doP && !doC) break;
        __syncthreads();
        if (w >= 8) {
            if (doP) {
                __nv_bfloat16* Ah = sb + OFF_A + par * 2 * TMWS;
                gather_tile(Hprev, offs, csr, Ah, Ah + TMWS, tp * TM, nrows, w - 8, lane);
            }
        } else if (doC) {
            const __nv_bfloat16* Ah = sb + OFF_A + (par ^ 1) * 2 * TMWS;
            float acc[4][4];
            mma_tile(Ah, Ah + TMWS, sW1h, sW1l, mrow0, nbase, lane, acc);
            int r0 = mrow0 + (lane >> 2);
#pragma unroll
            for (int j = 0; j < 4; j++) {
                int c = nbase + 8 * j + (lane & 3) * 2;
                float bx = __ldg(b1 + c), by = __ldg(b1 + c + 1);
                __nv_bfloat162 ph, pl;
                splitf(fmaxf(acc[j][0] + bx, 0.f), ph.x, pl.x);
                splitf(fmaxf(acc[j][1] + by, 0.f), ph.y, pl.y);
                *(__nv_bfloat162*)(sTh + r0 * WS + c) = ph;
                *(__nv_bfloat162*)(sTl + r0 * WS + c) = pl;
                splitf(fmaxf(acc[j][2] + bx, 0.f), ph.x, pl.x);
                splitf(fmaxf(acc[j][3] + by, 0.f), ph.y, pl.y);
                *(__nv_bfloat162*)(sTh + (r0 + 8) * WS + c) = ph;
                *(__nv_bfloat162*)(sTl + (r0 + 8) * WS + c) = pl;
            }
            asm volatile("bar.sync 1, 256;" ::: "memory");   // consumer-only barrier
            mma_tile(sTh, sTl, sW2h, sW2l, mrow0, nbase, lane, acc);
            int row0 = tc * TM;
#pragma unroll
            for (int j = 0; j < 4; j++) {
                int c = nbase + 8 * j + (lane & 3) * 2;
                float bx = __ldg(b2 + c), by = __ldg(b2 + c + 1);
                int gr0 = row0 + r0, gr1 = gr0 + 8;
                if (gr0 < nrows)
                    *(float2*)(Out + (size_t)gr0 * HN + c) =
                        make_float2(fmaxf(acc[j][0] + bx, 0.f), fmaxf(acc[j][1] + by, 0.f));
                if (gr1 < nrows)
                    *(float2*)(Out + (size_t)gr1 * HN + c) =
                        make_float2(fmaxf(acc[j][2] + bx, 0.f), fmaxf(acc[j][3] + by, 0.f));
            }
        }
        tc = doP ? tp : -1;
        tp += gridDim.x;
        par ^= 1;
    }
}

// ---------------- pooling: direct nodes -> graphs (comp sorted) ----------------
__global__ void k_comp(const int* __restrict__ sub, const int* __restrict__ s2g,
                       int* __restrict__ comp, int n) {
    int i = blockIdx.x * blockDim.x + threadIdx.x;
    if (i < n) comp[i] = s2g[sub[i]];
}
__global__ void k_pool(const float* __restrict__ h, const int* __restrict__ comp,
                       float* __restrict__ out, int N) {
    int j = threadIdx.x;
    int per = (N + gridDim.x - 1) / gridDim.x;
    int n0 = blockIdx.x * per;
    int n1 = n0 + per; if (n1 > N) n1 = N;
    if (n0 >= n1) return;
    float acc = 0.f;
    int cur = __ldg(comp + n0);
    for (int i = n0; i < n1; i++) {
        int c = __ldg(comp + i);
        if (c != cur) {
            atomicAdd(out + (size_t)cur * HN + j, acc);
            acc = 0.f; cur = c;
        }
        acc += __ldg(h + (size_t)i * HN + j);
    }
    atomicAdd(out + (size_t)cur * HN + j, acc);
}

// ---------------- launch ----------------
extern "C" void kernel_launch(void* const* d_in, const int* in_sizes, int n_in,
                              void* d_out, int out_size) {
    const float* x     = (const float*)d_in[0];
    const void*  ei    = d_in[1];
    const void*  n2s   = d_in[2];
    const void*  s2g_i = d_in[3];
    const float* c1W1  = (const float*)d_in[4];
    const float* c1b1  = (const float*)d_in[5];
    const float* c1W2  = (const float*)d_in[6];
    const float* c1b2  = (const float*)d_in[7];
    const float* cW1   = (const float*)d_in[8];
    const float* cb1   = (const float*)d_in[9];
    const float* cW2   = (const float*)d_in[10];
    const float* cb2   = (const float*)d_in[11];

    int N = in_sizes[0];
    int E = in_sizes[1] / 2;
    int S = in_sizes[3];
    int G = out_size / HN;

    float *bufA, *bufB, *agg0;
    int *eiX, *sub, *s2gX, *comp, *deg, *offs, *cursor, *csr;
    __nv_bfloat16* ws;
    cudaGetSymbolAddress((void**)&bufA,   g_bufA);
    cudaGetSymbolAddress((void**)&bufB,   g_bufB);
    cudaGetSymbolAddress((void**)&agg0,   g_agg0);
    cudaGetSymbolAddress((void**)&eiX,    g_ei);
    cudaGetSymbolAddress((void**)&sub,    g_sub);
    cudaGetSymbolAddress((void**)&s2gX,   g_s2g);
    cudaGetSymbolAddress((void**)&comp,   g_comp);
    cudaGetSymbolAddress((void**)&deg,    g_deg);
    cudaGetSymbolAddress((void**)&offs,   g_offs);
    cudaGetSymbolAddress((void**)&cursor, g_cursor);
    cudaGetSymbolAddress((void**)&csr,    g_csr);
    cudaGetSymbolAddress((void**)&ws,     g_wsplit);

    const int SMEM = SMEM_ELEMS * 2;   // 191488 B
    cudaFuncSetAttribute(k_layer, cudaFuncAttributeMaxDynamicSharedMemorySize, SMEM);

    // normalize index dtypes
    k_detect<<<1, 1>>>((const unsigned long long*)ei);
    k_convert<<<(2 * E + 255) / 256, 256>>>(ei, eiX, 2 * E);
    k_convert<<<(N + 255) / 256, 256>>>(n2s, sub, N);
    k_convert<<<(S + 255) / 256, 256>>>(s2g_i, s2gX, S);
    k_comp<<<(N + 255) / 256, 256>>>(sub, s2gX, comp, N);

    // split the 5 weight matrices into bf16 hi/lo planes
    k_splitW<<<64, 256>>>(c1W2,          ws + 0 * 2 * PLANE, ws + 0 * 2 * PLANE + PLANE);
    k_splitW<<<64, 256>>>(cW1,           ws + 1 * 2 * PLANE, ws + 1 * 2 * PLANE + PLANE);
    k_splitW<<<64, 256>>>(cW2,           ws + 2 * 2 * PLANE, ws + 2 * 2 * PLANE + PLANE);
    k_splitW<<<64, 256>>>(cW1 + HN * HN, ws + 3 * 2 * PLANE, ws + 3 * 2 * PLANE + PLANE);
    k_splitW<<<64, 256>>>(cW2 + HN * HN, ws + 4 * 2 * PLANE, ws + 4 * 2 * PLANE + PLANE);

    // CSR build (dst-major)
    k_zeroi<<<(N + 255) / 256, 256>>>(deg, N);
    k_hist<<<(E + 255) / 256, 256>>>(eiX + E, deg, E);
    k_scan<<<1, 1024>>>(deg, offs, N);
    k_zeroi<<<(N + 255) / 256, 256>>>(cursor, N);
    k_scatter<<<(E + 255) / 256, 256>>>(eiX, eiX + E, offs, cursor, csr, E);

    int ablocks = (N * 32 + 255) / 256;
    const int LGRID = 148;

    // layer 1: scalar agg + fused expansion/MMA
    k_agg0<<<ablocks, 256>>>(offs, csr, x, agg0, N);
    k_layer<<<LGRID, 384, SMEM>>>(nullptr, nullptr, nullptr, agg0, c1W1,
                                  nullptr, nullptr, c1b1,
                                  ws + 0 * 2 * PLANE, ws + 0 * 2 * PLANE + PLANE, c1b2,
                                  bufB, N, 0);

    // layer 2: fused gather + dual MMA (bufB -> bufA)
    k_layer<<<LGRID, 384, SMEM>>>(bufB, offs, csr, nullptr, nullptr,
                                  ws + 1 * 2 * PLANE, ws + 1 * 2 * PLANE + PLANE, cb1,
                                  ws + 2 * 2 * PLANE, ws + 2 * 2 * PLANE + PLANE, cb2,
                                  bufA, N, 1);
    // layer 3: fused gather + dual MMA (bufA -> bufB)
    k_layer<<<LGRID, 384, SMEM>>>(bufA, offs, csr, nullptr, nullptr,
                                  ws + 3 * 2 * PLANE, ws + 3 * 2 * PLANE + PLANE, cb1 + HN,
                                  ws + 4 * 2 * PLANE, ws + 4 * 2 * PLANE + PLANE, cb2 + HN,
                                  bufB, N, 1);

    // pooling: nodes -> graphs via composed index
    k_zero4<<<((G * HN / 4) + 255) / 256, 256>>>((float*)d_out, G * HN / 4);
    k_pool<<<512, HN>>>(bufB, comp, (float*)d_out, N);
}

// round 8
// speedup vs baseline: 2.2047x; 2.2047x over previous
#include <cuda_runtime.h>
#include <cuda_bf16.h>
#include <cstdint>

#define HN   128
#define MAXN 100000
#define MAXE 1600000
#define MAXS 10000
#define TM   64
#define WS   136            // padded bf16 plane stride (ldsm conflict-free)
#define PLANE (HN * WS)     // 17408
#define TMWS  (TM * WS)     // 8704

// ---------------- scratch (static device globals; no allocation) ----------------
__device__ __align__(16) __nv_bfloat16 g_hA[(size_t)MAXN * HN];
__device__ __align__(16) __nv_bfloat16 g_hB[(size_t)MAXN * HN];
__device__ float g_agg0[MAXN];
__device__ int   g_ei[2 * MAXE];
__device__ int   g_sub[MAXN];
__device__ int   g_s2g[MAXS];
__device__ int   g_comp[MAXN];
__device__ int   g_deg[MAXN];
__device__ int   g_offs[MAXN + 1];
__device__ int   g_cursor[MAXN];
__device__ int   g_csr[MAXE];
__device__ int   g_is64;
__device__ __align__(16) __nv_bfloat16 g_wsplit[5 * 2 * PLANE];

// ---------------- helpers ----------------
__device__ __forceinline__ uint32_t sptr(const void* p) {
    return (uint32_t)__cvta_generic_to_shared(p);
}
__device__ __forceinline__ void splitf(float x, __nv_bfloat16& h, __nv_bfloat16& l) {
    h = __float2bfloat16(x);
    l = __float2bfloat16(x - __bfloat162float(h));
}
__device__ __forceinline__ void ldsm4(uint32_t a, uint32_t& r0, uint32_t& r1,
                                      uint32_t& r2, uint32_t& r3) {
    asm volatile("ldmatrix.sync.aligned.m8n8.x4.shared.b16 {%0,%1,%2,%3},[%4];"
                 : "=r"(r0), "=r"(r1), "=r"(r2), "=r"(r3) : "r"(a));
}
__device__ __forceinline__ void ldsm4t(uint32_t a, uint32_t& r0, uint32_t& r1,
                                       uint32_t& r2, uint32_t& r3) {
    asm volatile("ldmatrix.sync.aligned.m8n8.x4.trans.shared.b16 {%0,%1,%2,%3},[%4];"
                 : "=r"(r0), "=r"(r1), "=r"(r2), "=r"(r3) : "r"(a));
}
__device__ __forceinline__ void mma16816(float* c, uint32_t a0, uint32_t a1, uint32_t a2,
                                         uint32_t a3, uint32_t b0, uint32_t b1) {
    asm volatile(
        "mma.sync.aligned.m16n8k16.row.col.f32.bf16.bf16.f32 "
        "{%0,%1,%2,%3},{%4,%5,%6,%7},{%8,%9},{%0,%1,%2,%3};"
        : "+f"(c[0]), "+f"(c[1]), "+f"(c[2]), "+f"(c[3])
        : "r"(a0), "r"(a1), "r"(a2), "r"(a3), "r"(b0), "r"(b1));
}

// ---------------- index dtype detection + normalization ----------------
__global__ void k_detect(const unsigned long long* __restrict__ p) {
    if (blockIdx.x == 0 && threadIdx.x == 0) {
        int is64 = 1;
        for (int i = 0; i < 64; i++)
            if (p[i] >> 32) { is64 = 0; break; }
        g_is64 = is64;
    }
}
// convert both halves of edge_index; histogram degrees from the dst half
__global__ void k_convert_ei(const void* __restrict__ in, int* __restrict__ out,
                             int* __restrict__ deg, int E) {
    int i = blockIdx.x * blockDim.x + threadIdx.x;
    if (i >= 2 * E) return;
    int v;
    if (g_is64) v = (int)(((const long long*)in)[i]);
    else        v = ((const int*)in)[i];
    out[i] = v;
    if (i >= E) atomicAdd(deg + v, 1);
}
__global__ void k_convert(const void* __restrict__ in, int* __restrict__ out, int n) {
    int i = blockIdx.x * blockDim.x + threadIdx.x;
    if (i >= n) return;
    if (g_is64) out[i] = (int)(((const long long*)in)[i]);
    else        out[i] = ((const int*)in)[i];
}

// ---------------- utility ----------------
__global__ void k_zero4(float* __restrict__ p, int n4) {
    int i = blockIdx.x * blockDim.x + threadIdx.x;
    if (i < n4) ((float4*)p)[i] = make_float4(0.f, 0.f, 0.f, 0.f);
}
__global__ void k_zeroi(int* __restrict__ p, int n) {
    int i = blockIdx.x * blockDim.x + threadIdx.x;
    if (i < n) p[i] = 0;
}

// ---------------- W split ----------------
__global__ void k_splitW(const float* __restrict__ W, __nv_bfloat16* __restrict__ dh,
                         __nv_bfloat16* __restrict__ dl) {
    int i = blockIdx.x * blockDim.x + threadIdx.x;
    if (i >= HN * HN) return;
    int k = i >> 7, n = i & 127;
    __nv_bfloat16 h, l;
    splitf(W[i], h, l);
    dh[k * WS + n] = h;
    dl[k * WS + n] = l;
}

// ---------------- CSR build ----------------
__global__ void k_scan(const int* __restrict__ deg, int* __restrict__ offs, int n) {
    __shared__ int sums[1024];
    int tid = threadIdx.x;
    int chunk = (n + 1023) / 1024;
    int start = tid * chunk;
    int end   = start + chunk; if (end > n) end = n;
    int s = 0;
    for (int i = start; i < end; i++) s += deg[i];
    sums[tid] = s;
    __syncthreads();
    for (int off = 1; off < 1024; off <<= 1) {
        int v = 0;
        if (tid >= off) v = sums[tid - off];
        __syncthreads();
        if (tid >= off) sums[tid] += v;
        __syncthreads();
    }
    int run = (tid == 0) ? 0 : sums[tid - 1];
    for (int i = start; i < end; i++) { offs[i] = run; run += deg[i]; }
    if (end == n) offs[n] = run;
}
__global__ void k_scatter(const int* __restrict__ src, const int* __restrict__ dst,
                          const int* __restrict__ offs, int* __restrict__ cursor,
                          int* __restrict__ csr, int E) {
    int e = blockIdx.x * blockDim.x + threadIdx.x;
    if (e >= E) return;
    int d = dst[e];
    int p = atomicAdd(cursor + d, 1);
    csr[offs[d] + p] = src[e];
}

// ---------------- layer-1 scalar aggregation ----------------
__global__ void k_agg0(const int* __restrict__ offs, const int* __restrict__ csr,
                       const float* __restrict__ x, float* __restrict__ agg, int N) {
    int warp = (blockIdx.x * blockDim.x + threadIdx.x) >> 5;
    int lane = threadIdx.x & 31;
    if (warp >= N) return;
    int s = offs[warp], e = offs[warp + 1];
    float acc = 0.f;
    for (int i = s + lane; i < e; i += 32) acc += __ldg(x + csr[i]);
#pragma unroll
    for (int o = 16; o; o >>= 1) acc += __shfl_xor_sync(0xffffffffu, acc, o);
    if (lane == 0) agg[warp] = acc + x[warp];
}

// ---------------- bf16 vector aggregation incl. self ----------------
// warp per node; lane handles 4 cols (8B). fp32 accumulate, bf16 out.
__device__ __forceinline__ void addbf2(float4& a, uint2 v) {
    float2 f0 = __bfloat1622float2(*(__nv_bfloat162*)&v.x);
    float2 f1 = __bfloat1622float2(*(__nv_bfloat162*)&v.y);
    a.x += f0.x; a.y += f0.y; a.z += f1.x; a.w += f1.y;
}
__global__ __launch_bounds__(256) void k_agg_csr(
    const int* __restrict__ offs, const int* __restrict__ csr,
    const __nv_bfloat16* __restrict__ h, __nv_bfloat16* __restrict__ out, int N) {
    int warp = (blockIdx.x * blockDim.x + threadIdx.x) >> 5;
    int lane = threadIdx.x & 31;
    if (warp >= N) return;
    int s = offs[warp], e = offs[warp + 1];
    float4 acc = make_float4(0.f, 0.f, 0.f, 0.f);
    addbf2(acc, __ldg(((const uint2*)(h + (size_t)warp * HN)) + lane));   // self
    int i = s;
#pragma unroll 1
    for (; i + 8 <= e; i += 8) {
        int idx[8];
#pragma unroll
        for (int u = 0; u < 8; u++) idx[u] = __ldg(csr + i + u);
        uint2 v[8];
#pragma unroll
        for (int u = 0; u < 8; u++)
            v[u] = __ldg(((const uint2*)(h + (size_t)idx[u] * HN)) + lane);
#pragma unroll
        for (int u = 0; u < 8; u++) addbf2(acc, v[u]);
    }
    for (; i < e; i++)
        addbf2(acc, __ldg(((const uint2*)(h + (size_t)__ldg(csr + i) * HN)) + lane));
    uint2 o;
    __nv_bfloat162 p0 = __floats2bfloat162_rn(acc.x, acc.y);
    __nv_bfloat162 p1 = __floats2bfloat162_rn(acc.z, acc.w);
    o.x = *(uint32_t*)&p0; o.y = *(uint32_t*)&p1;
    ((uint2*)(out + (size_t)warp * HN))[lane] = o;
}

// ---------------- MMA: acc[8][4] = A[64,128]bf16 @ (Wh+Wl)[128,128] ----------------
__device__ __forceinline__ void mma_phase(
    const __nv_bfloat16* A,
    const __nv_bfloat16* Bh, const __nv_bfloat16* Bl,
    int mrow0, int nbase, int lane, float acc[8][4]) {
#pragma unroll
    for (int j = 0; j < 8; j++)
#pragma unroll
        for (int c = 0; c < 4; c++) acc[j][c] = 0.f;

    int aoff = (mrow0 + (lane & 15)) * WS + ((lane >> 4) << 3);
    int brow = (lane & 15) * WS;
    int bn   = (lane >> 4) << 3;

#pragma unroll
    for (int kt = 0; kt < 8; kt++) {
        uint32_t a0, a1, a2, a3;
        ldsm4(sptr(A + aoff + kt * 16), a0, a1, a2, a3);
#pragma unroll
        for (int jj = 0; jj < 4; jj++) {
            int nj = nbase + jj * 16;
            uint32_t bh0, bh1, bh2, bh3, bl0, bl1, bl2, bl3;
            ldsm4t(sptr(Bh + kt * 16 * WS + brow + nj + bn), bh0, bh1, bh2, bh3);
            ldsm4t(sptr(Bl + kt * 16 * WS + brow + nj + bn), bl0, bl1, bl2, bl3);
            mma16816(acc[2 * jj],     a0, a1, a2, a3, bh0, bh1);
            mma16816(acc[2 * jj],     a0, a1, a2, a3, bl0, bl1);
            mma16816(acc[2 * jj + 1], a0, a1, a2, a3, bh2, bh3);
            mma16816(acc[2 * jj + 1], a0, a1, a2, a3, bl2, bl3);
        }
    }
}

// ---------------- fused GIN layer (persistent, tensor-core, bf16 I/O) ----------------
// smem: W1h W1l W2h W2l (PLANE each) + A (TMWS) + T (TMWS) = 87040 elems = 174080 B
#define OFF_A (4 * PLANE)
#define OFF_T (4 * PLANE + TMWS)
#define SMEM_ELEMS (4 * PLANE + 2 * TMWS)

extern __shared__ __nv_bfloat16 sb[];

__global__ __launch_bounds__(256) void k_layer(
    const __nv_bfloat16* __restrict__ A, const float* __restrict__ vscal,
    const float* __restrict__ W1v,
    const __nv_bfloat16* __restrict__ W1h, const __nv_bfloat16* __restrict__ W1l,
    const float* __restrict__ b1,
    const __nv_bfloat16* __restrict__ W2h, const __nv_bfloat16* __restrict__ W2l,
    const float* __restrict__ b2,
    __nv_bfloat16* __restrict__ Out, int nrows, int mode) {

    __shared__ float sv[TM];
    int tid  = threadIdx.x;
    int lane = tid & 31;
    int w    = tid >> 5;
    int mrow0 = (w >> 1) * 16;
    int nbase = (w & 1) * 64;

    __nv_bfloat16* sW1h = sb;
    __nv_bfloat16* sW1l = sb + PLANE;
    __nv_bfloat16* sW2h = sb + 2 * PLANE;
    __nv_bfloat16* sW2l = sb + 3 * PLANE;
    __nv_bfloat16* sA   = sb + OFF_A;
    __nv_bfloat16* sT   = sb + OFF_T;

    const int U4 = PLANE * 2 / 16;
    for (int i = tid; i < U4; i += 256) {
        ((uint4*)sW2h)[i] = ((const uint4*)W2h)[i];
        ((uint4*)sW2l)[i] = ((const uint4*)W2l)[i];
        if (mode == 1) {
            ((uint4*)sW1h)[i] = ((const uint4*)W1h)[i];
            ((uint4*)sW1l)[i] = ((const uint4*)W1l)[i];
        }
    }

    int ntiles = (nrows + TM - 1) / TM;
    for (int t = blockIdx.x; t < ntiles; t += gridDim.x) {
        int row0 = t * TM;
        int tr = nrows - row0; if (tr > TM) tr = TM;
        __syncthreads();

        if (mode == 0) {
            if (tid < TM) sv[tid] = (tid < tr) ? vscal[row0 + tid] : 0.f;
            __syncthreads();
            for (int i = tid; i < TM * HN; i += 256) {
                int r = i >> 7, c = i & 127;
                float v = fmaxf(fmaf(sv[r], __ldg(W1v + c), __ldg(b1 + c)), 0.f);
                sT[r * WS + c] = __float2bfloat16(v);
            }
            __syncthreads();
        } else {
            // load A tile (bf16, 8 elems per uint4)
            for (int i = tid; i < TM * HN / 8; i += 256) {
                int e = i * 8, r = e >> 7, c = e & 127;
                uint4 v = make_uint4(0u, 0u, 0u, 0u);
                if (r < tr) v = __ldg((const uint4*)(A + (size_t)(row0 + r) * HN + c));
                *(uint4*)(sA + r * WS + c) = v;
            }
            __syncthreads();

            float acc[8][4];
            mma_phase(sA, sW1h, sW1l, mrow0, nbase, lane, acc);

            int r0 = mrow0 + (lane >> 2);
#pragma unroll
            for (int j = 0; j < 8; j++) {
                int c = nbase + 8 * j + (lane & 3) * 2;
                float bx = __ldg(b1 + c), by = __ldg(b1 + c + 1);
                *(__nv_bfloat162*)(sT + r0 * WS + c) =
                    __floats2bfloat162_rn(fmaxf(acc[j][0] + bx, 0.f), fmaxf(acc[j][1] + by, 0.f));
                *(__nv_bfloat162*)(sT + (r0 + 8) * WS + c) =
                    __floats2bfloat162_rn(fmaxf(acc[j][2] + bx, 0.f), fmaxf(acc[j][3] + by, 0.f));
            }
            __syncthreads();
        }

        // phase 2: Out = relu(T @ W2 + b2), bf16 out
        float acc[8][4];
        mma_phase(sT, sW2h, sW2l, mrow0, nbase, lane, acc);

        int r0 = mrow0 + (lane >> 2);
#pragma unroll
        for (int j = 0; j < 8; j++) {
            int c = nbase + 8 * j + (lane & 3) * 2;
            float bx = __ldg(b2 + c), by = __ldg(b2 + c + 1);
            int gr0 = row0 + r0, gr1 = gr0 + 8;
            if (gr0 < nrows)
                *(__nv_bfloat162*)(Out + (size_t)gr0 * HN + c) =
                    __floats2bfloat162_rn(fmaxf(acc[j][0] + bx, 0.f), fmaxf(acc[j][1] + by, 0.f));
            if (gr1 < nrows)
                *(__nv_bfloat162*)(Out + (size_t)gr1 * HN + c) =
                    __floats2bfloat162_rn(fmaxf(acc[j][2] + bx, 0.f), fmaxf(acc[j][3] + by, 0.f));
        }
    }
}

// ---------------- pooling: bf16 nodes -> fp32 graphs (comp sorted) ----------------
__global__ void k_comp(const int* __restrict__ sub, const int* __restrict__ s2g,
                       int* __restrict__ comp, int n) {
    int i = blockIdx.x * blockDim.x + threadIdx.x;
    if (i < n) comp[i] = s2g[sub[i]];
}
__global__ void k_pool(const __nv_bfloat16* __restrict__ h, const int* __restrict__ comp,
                       float* __restrict__ out, int N) {
    int j = threadIdx.x;   // 0..127
    int per = (N + gridDim.x - 1) / gridDim.x;
    int n0 = blockIdx.x * per;
    int n1 = n0 + per; if (n1 > N) n1 = N;
    if (n0 >= n1) return;
    float acc = 0.f;
    int cur = __ldg(comp + n0);
    for (int i = n0; i < n1; i++) {
        int c = __ldg(comp + i);
        if (c != cur) {
            atomicAdd(out + (size_t)cur * HN + j, acc);
            acc = 0.f; cur = c;
        }
        acc += __bfloat162float(__ldg(h + (size_t)i * HN + j));
    }
    atomicAdd(out + (size_t)cur * HN + j, acc);
}

// ---------------- launch ----------------
extern "C" void kernel_launch(void* const* d_in, const int* in_sizes, int n_in,
                              void* d_out, int out_size) {
    const float* x     = (const float*)d_in[0];
    const void*  ei    = d_in[1];
    const void*  n2s   = d_in[2];
    const void*  s2g_i = d_in[3];
    const float* c1W1  = (const float*)d_in[4];
    const float* c1b1  = (const float*)d_in[5];
    const float* c1W2  = (const float*)d_in[6];
    const float* c1b2  = (const float*)d_in[7];
    const float* cW1   = (const float*)d_in[8];
    const float* cb1   = (const float*)d_in[9];
    const float* cW2   = (const float*)d_in[10];
    const float* cb2   = (const float*)d_in[11];

    int N = in_sizes[0];
    int E = in_sizes[1] / 2;
    int S = in_sizes[3];
    int G = out_size / HN;

    __nv_bfloat16 *hA, *hB, *ws;
    float *agg0;
    int *eiX, *sub, *s2gX, *comp, *deg, *offs, *cursor, *csr;
    cudaGetSymbolAddress((void**)&hA,     g_hA);
    cudaGetSymbolAddress((void**)&hB,     g_hB);
    cudaGetSymbolAddress((void**)&agg0,   g_agg0);
    cudaGetSymbolAddress((void**)&eiX,    g_ei);
    cudaGetSymbolAddress((void**)&sub,    g_sub);
    cudaGetSymbolAddress((void**)&s2gX,   g_s2g);
    cudaGetSymbolAddress((void**)&comp,   g_comp);
    cudaGetSymbolAddress((void**)&deg,    g_deg);
    cudaGetSymbolAddress((void**)&offs,   g_offs);
    cudaGetSymbolAddress((void**)&cursor, g_cursor);
    cudaGetSymbolAddress((void**)&csr,    g_csr);
    cudaGetSymbolAddress((void**)&ws,     g_wsplit);

    const int SMEM = SMEM_ELEMS * 2;   // 174080 B
    cudaFuncSetAttribute(k_layer, cudaFuncAttributeMaxDynamicSharedMemorySize, SMEM);

    // normalize index dtypes (+ fused degree histogram)
    k_detect<<<1, 1>>>((const unsigned long long*)ei);
    k_zeroi<<<(N + 255) / 256, 256>>>(deg, N);
    k_convert_ei<<<(2 * E + 255) / 256, 256>>>(ei, eiX, deg, E);
    k_convert<<<(N + 255) / 256, 256>>>(n2s, sub, N);
    k_convert<<<(S + 255) / 256, 256>>>(s2g_i, s2gX, S);
    k_comp<<<(N + 255) / 256, 256>>>(sub, s2gX, comp, N);

    // split the 5 weight matrices into bf16 hi/lo planes
    k_splitW<<<64, 256>>>(c1W2,          ws + 0 * 2 * PLANE, ws + 0 * 2 * PLANE + PLANE);
    k_splitW<<<64, 256>>>(cW1,           ws + 1 * 2 * PLANE, ws + 1 * 2 * PLANE + PLANE);
    k_splitW<<<64, 256>>>(cW2,           ws + 2 * 2 * PLANE, ws + 2 * 2 * PLANE + PLANE);
    k_splitW<<<64, 256>>>(cW1 + HN * HN, ws + 3 * 2 * PLANE, ws + 3 * 2 * PLANE + PLANE);
    k_splitW<<<64, 256>>>(cW2 + HN * HN, ws + 4 * 2 * PLANE, ws + 4 * 2 * PLANE + PLANE);

    // CSR build (dst-major)
    k_scan<<<1, 1024>>>(deg, offs, N);
    k_zeroi<<<(N + 255) / 256, 256>>>(cursor, N);
    k_scatter<<<(E + 255) / 256, 256>>>(eiX, eiX + E, offs, cursor, csr, E);

    int ablocks = (N * 32 + 255) / 256;
    const int LGRID = 148;

    // layer 1: scalar agg + fused expansion/MMA -> hB (bf16)
    k_agg0<<<ablocks, 256>>>(offs, csr, x, agg0, N);
    k_layer<<<LGRID, 256, SMEM>>>(nullptr, agg0, c1W1, nullptr, nullptr, c1b1,
                                  ws + 0 * 2 * PLANE, ws + 0 * 2 * PLANE + PLANE, c1b2,
                                  hB, N, 0);

    // layers 2..3: bf16 CSR agg + fused dual MMA
    for (int i = 0; i < 2; i++) {
        k_agg_csr<<<ablocks, 256>>>(offs, csr, hB, hA, N);
        k_layer<<<LGRID, 256, SMEM>>>(hA, nullptr, nullptr,
                                      ws + (1 + 2 * i) * 2 * PLANE,
                                      ws + (1 + 2 * i) * 2 * PLANE + PLANE,
                                      cb1 + (size_t)i * HN,
                                      ws + (2 + 2 * i) * 2 * PLANE,
                                      ws + (2 + 2 * i) * 2 * PLANE + PLANE,
                                      cb2 + (size_t)i * HN,
                                      hB, N, 1);
    }

    // pooling: nodes -> graphs via composed index
    k_zero4<<<((G * HN / 4) + 255) / 256, 256>>>((float*)d_out, G * HN / 4);
    k_pool<<<1024, HN>>>(hB, comp, (float*)d_out, N);
}

// round 9
// speedup vs baseline: 2.6398x; 1.1974x over previous
#include <cuda_runtime.h>
#include <cuda_fp16.h>
#include <cstdint>

#define HN   128
#define MAXN 100000
#define MAXE 1600000
#define MAXS 10000
#define TM   64
#define WS   136            // padded fp16 plane stride (ldsm conflict-free)
#define PLANE (HN * WS)     // 17408
#define TMWS  (TM * WS)     // 8704

// ---------------- scratch (static device globals; no allocation) ----------------
__device__ __align__(16) __half g_hA[(size_t)MAXN * HN];
__device__ __align__(16) __half g_hB[(size_t)MAXN * HN];
__device__ float g_agg0[MAXN];
__device__ int   g_ei[2 * MAXE];
__device__ int   g_comp[MAXN];
__device__ int   g_deg[MAXN];
__device__ int   g_offs[MAXN + 1];
__device__ int   g_cursor[MAXN];
__device__ int   g_csr[MAXE];
__device__ int   g_is64;
__device__ __align__(16) __half g_whalf[5 * PLANE];   // 5 matrices, single fp16 plane each

// ---------------- helpers ----------------
__device__ __forceinline__ uint32_t sptr(const void* p) {
    return (uint32_t)__cvta_generic_to_shared(p);
}
__device__ __forceinline__ void ldsm4(uint32_t a, uint32_t& r0, uint32_t& r1,
                                      uint32_t& r2, uint32_t& r3) {
    asm volatile("ldmatrix.sync.aligned.m8n8.x4.shared.b16 {%0,%1,%2,%3},[%4];"
                 : "=r"(r0), "=r"(r1), "=r"(r2), "=r"(r3) : "r"(a));
}
__device__ __forceinline__ void ldsm4t(uint32_t a, uint32_t& r0, uint32_t& r1,
                                       uint32_t& r2, uint32_t& r3) {
    asm volatile("ldmatrix.sync.aligned.m8n8.x4.trans.shared.b16 {%0,%1,%2,%3},[%4];"
                 : "=r"(r0), "=r"(r1), "=r"(r2), "=r"(r3) : "r"(a));
}
__device__ __forceinline__ void mma16816(float* c, uint32_t a0, uint32_t a1, uint32_t a2,
                                         uint32_t a3, uint32_t b0, uint32_t b1) {
    asm volatile(
        "mma.sync.aligned.m16n8k16.row.col.f32.f16.f16.f32 "
        "{%0,%1,%2,%3},{%4,%5,%6,%7},{%8,%9},{%0,%1,%2,%3};"
        : "+f"(c[0]), "+f"(c[1]), "+f"(c[2]), "+f"(c[3])
        : "r"(a0), "r"(a1), "r"(a2), "r"(a3), "r"(b0), "r"(b1));
}

// ---------------- index dtype detection + normalization ----------------
__global__ void k_detect(const unsigned long long* __restrict__ p) {
    if (blockIdx.x == 0 && threadIdx.x == 0) {
        int is64 = 1;
        for (int i = 0; i < 64; i++)
            if (p[i] >> 32) { is64 = 0; break; }
        g_is64 = is64;
    }
}
// convert both halves of edge_index; histogram degrees from the dst half
__global__ void k_convert_ei(const void* __restrict__ in, int* __restrict__ out,
                             int* __restrict__ deg, int E) {
    int i = blockIdx.x * blockDim.x + threadIdx.x;
    if (i >= 2 * E) return;
    int v;
    if (g_is64) v = (int)(((const long long*)in)[i]);
    else        v = ((const int*)in)[i];
    out[i] = v;
    if (i >= E) atomicAdd(deg + v, 1);
}
// comp[i] = s2g[n2s[i]] straight from raw inputs
__global__ void k_comp2(const void* __restrict__ n2s, const void* __restrict__ s2g,
                        int* __restrict__ comp, int n) {
    int i = blockIdx.x * blockDim.x + threadIdx.x;
    if (i >= n) return;
    int s, g;
    if (g_is64) {
        s = (int)(((const long long*)n2s)[i]);
        g = (int)(((const long long*)s2g)[s]);
    } else {
        s = ((const int*)n2s)[i];
        g = ((const int*)s2g)[s];
    }
    comp[i] = g;
}

// ---------------- utility ----------------
__global__ void k_zero4(float* __restrict__ p, int n4) {
    int i = blockIdx.x * blockDim.x + threadIdx.x;
    if (i < n4) ((float4*)p)[i] = make_float4(0.f, 0.f, 0.f, 0.f);
}
__global__ void k_zeroi(int* __restrict__ p, int n) {
    int i = blockIdx.x * blockDim.x + threadIdx.x;
    if (i < n) p[i] = 0;
}

// ---------------- W convert: fp32 [128,128] -> fp16 plane (stride WS) ----------------
__global__ void k_cvtW(const float* __restrict__ W, __half* __restrict__ d) {
    int i = blockIdx.x * blockDim.x + threadIdx.x;
    if (i >= HN * HN) return;
    int k = i >> 7, n = i & 127;
    d[k * WS + n] = __float2half_rn(W[i]);
}

// ---------------- CSR build ----------------
__global__ void k_scan(const int* __restrict__ deg, int* __restrict__ offs, int n) {
    __shared__ int sums[1024];
    int tid = threadIdx.x;
    int chunk = (n + 1023) / 1024;
    int start = tid * chunk;
    int end   = start + chunk; if (end > n) end = n;
    int s = 0;
    for (int i = start; i < end; i++) s += deg[i];
    sums[tid] = s;
    __syncthreads();
    for (int off = 1; off < 1024; off <<= 1) {
        int v = 0;
        if (tid >= off) v = sums[tid - off];
        __syncthreads();
        if (tid >= off) sums[tid] += v;
        __syncthreads();
    }
    int run = (tid == 0) ? 0 : sums[tid - 1];
    for (int i = start; i < end; i++) { offs[i] = run; run += deg[i]; }
    if (end == n) offs[n] = run;
}
__global__ void k_scatter(const int* __restrict__ src, const int* __restrict__ dst,
                          const int* __restrict__ offs, int* __restrict__ cursor,
                          int* __restrict__ csr, int E) {
    int e = blockIdx.x * blockDim.x + threadIdx.x;
    if (e >= E) return;
    int d = dst[e];
    int p = atomicAdd(cursor + d, 1);
    csr[offs[d] + p] = src[e];
}

// ---------------- layer-1 scalar aggregation ----------------
__global__ void k_agg0(const int* __restrict__ offs, const int* __restrict__ csr,
                       const float* __restrict__ x, float* __restrict__ agg, int N) {
    int warp = (blockIdx.x * blockDim.x + threadIdx.x) >> 5;
    int lane = threadIdx.x & 31;
    if (warp >= N) return;
    int s = offs[warp], e = offs[warp + 1];
    float acc = 0.f;
    for (int i = s + lane; i < e; i += 32) acc += __ldg(x + csr[i]);
#pragma unroll
    for (int o = 16; o; o >>= 1) acc += __shfl_xor_sync(0xffffffffu, acc, o);
    if (lane == 0) agg[warp] = acc + x[warp];
}

// ---------------- fp16 vector aggregation incl. self ----------------
__device__ __forceinline__ void addh2(float4& a, uint2 v) {
    float2 f0 = __half22float2(*(__half2*)&v.x);
    float2 f1 = __half22float2(*(__half2*)&v.y);
    a.x += f0.x; a.y += f0.y; a.z += f1.x; a.w += f1.y;
}
__global__ __launch_bounds__(256) void k_agg_csr(
    const int* __restrict__ offs, const int* __restrict__ csr,
    const __half* __restrict__ h, __half* __restrict__ out, int N) {
    int warp = (blockIdx.x * blockDim.x + threadIdx.x) >> 5;
    int lane = threadIdx.x & 31;
    if (warp >= N) return;
    int s = offs[warp], e = offs[warp + 1];
    float4 acc = make_float4(0.f, 0.f, 0.f, 0.f);
    addh2(acc, __ldg(((const uint2*)(h + (size_t)warp * HN)) + lane));   // self
    int i = s;
#pragma unroll 1
    for (; i + 8 <= e; i += 8) {
        int idx[8];
#pragma unroll
        for (int u = 0; u < 8; u++) idx[u] = __ldg(csr + i + u);
        uint2 v[8];
#pragma unroll
        for (int u = 0; u < 8; u++)
            v[u] = __ldg(((const uint2*)(h + (size_t)idx[u] * HN)) + lane);
#pragma unroll
        for (int u = 0; u < 8; u++) addh2(acc, v[u]);
    }
    for (; i < e; i++)
        addh2(acc, __ldg(((const uint2*)(h + (size_t)__ldg(csr + i) * HN)) + lane));
    uint2 o;
    __half2 p0 = __floats2half2_rn(acc.x, acc.y);
    __half2 p1 = __floats2half2_rn(acc.z, acc.w);
    o.x = *(uint32_t*)&p0; o.y = *(uint32_t*)&p1;
    ((uint2*)(out + (size_t)warp * HN))[lane] = o;
}

// ---------------- MMA: acc[8][4] = A[64,128]f16 @ W[128,128]f16 ----------------
__device__ __forceinline__ void mma_phase(
    const __half* A, const __half* B,
    int mrow0, int nbase, int lane, float acc[8][4]) {
#pragma unroll
    for (int j = 0; j < 8; j++)
#pragma unroll
        for (int c = 0; c < 4; c++) acc[j][c] = 0.f;

    int aoff = (mrow0 + (lane & 15)) * WS + ((lane >> 4) << 3);
    int brow = (lane & 15) * WS;
    int bn   = (lane >> 4) << 3;

#pragma unroll
    for (int kt = 0; kt < 8; kt++) {
        uint32_t a0, a1, a2, a3;
        ldsm4(sptr(A + aoff + kt * 16), a0, a1, a2, a3);
#pragma unroll
        for (int jj = 0; jj < 4; jj++) {
            int nj = nbase + jj * 16;
            uint32_t b0, b1, b2, b3;
            ldsm4t(sptr(B + kt * 16 * WS + brow + nj + bn), b0, b1, b2, b3);
            mma16816(acc[2 * jj],     a0, a1, a2, a3, b0, b1);
            mma16816(acc[2 * jj + 1], a0, a1, a2, a3, b2, b3);
        }
    }
}

// ---------------- fused GIN layer (persistent, tensor-core, fp16 I/O) ----------------
// smem: W1 (PLANE) + W2 (PLANE) + A (TMWS) + T (TMWS) = 52224 elems = 104448 B
#define OFF_A (2 * PLANE)
#define OFF_T (2 * PLANE + TMWS)
#define SMEM_ELEMS (2 * PLANE + 2 * TMWS)

extern __shared__ __half sb[];

__global__ __launch_bounds__(256) void k_layer(
    const __half* __restrict__ A, const float* __restrict__ vscal,
    const float* __restrict__ W1v,
    const __half* __restrict__ W1, const float* __restrict__ b1,
    const __half* __restrict__ W2, const float* __restrict__ b2,
    __half* __restrict__ Out, int nrows, int mode) {

    __shared__ float sv[TM];
    int tid  = threadIdx.x;
    int lane = tid & 31;
    int w    = tid >> 5;
    int mrow0 = (w >> 1) * 16;
    int nbase = (w & 1) * 64;

    __half* sW1 = sb;
    __half* sW2 = sb + PLANE;
    __half* sA  = sb + OFF_A;
    __half* sT  = sb + OFF_T;

    const int U4 = PLANE * 2 / 16;
    for (int i = tid; i < U4; i += 256) {
        ((uint4*)sW2)[i] = ((const uint4*)W2)[i];
        if (mode == 1) ((uint4*)sW1)[i] = ((const uint4*)W1)[i];
    }

    int ntiles = (nrows + TM - 1) / TM;
    for (int t = blockIdx.x; t < ntiles; t += gridDim.x) {
        int row0 = t * TM;
        int tr = nrows - row0; if (tr > TM) tr = TM;
        __syncthreads();

        if (mode == 0) {
            if (tid < TM) sv[tid] = (tid < tr) ? vscal[row0 + tid] : 0.f;
            __syncthreads();
            for (int i = tid; i < TM * HN; i += 256) {
                int r = i >> 7, c = i & 127;
                float v = fmaxf(fmaf(sv[r], __ldg(W1v + c), __ldg(b1 + c)), 0.f);
                sT[r * WS + c] = __float2half_rn(v);
            }
            __syncthreads();
        } else {
            // load A tile (fp16, 8 elems per uint4)
            for (int i = tid; i < TM * HN / 8; i += 256) {
                int e = i * 8, r = e >> 7, c = e & 127;
                uint4 v = make_uint4(0u, 0u, 0u, 0u);
                if (r < tr) v = __ldg((const uint4*)(A + (size_t)(row0 + r) * HN + c));
                *(uint4*)(sA + r * WS + c) = v;
            }
            __syncthreads();

            float acc[8][4];
            mma_phase(sA, sW1, mrow0, nbase, lane, acc);

            int r0 = mrow0 + (lane >> 2);
#pragma unroll
            for (int j = 0; j < 8; j++) {
                int c = nbase + 8 * j + (lane & 3) * 2;
                float bx = __ldg(b1 + c), by = __ldg(b1 + c + 1);
                *(__half2*)(sT + r0 * WS + c) =
                    __floats2half2_rn(fmaxf(acc[j][0] + bx, 0.f), fmaxf(acc[j][1] + by, 0.f));
                *(__half2*)(sT + (r0 + 8) * WS + c) =
                    __floats2half2_rn(fmaxf(acc[j][2] + bx, 0.f), fmaxf(acc[j][3] + by, 0.f));
            }
            __syncthreads();
        }

        // phase 2: Out = relu(T @ W2 + b2), fp16 out
        float acc[8][4];
        mma_phase(sT, sW2, mrow0, nbase, lane, acc);

        int r0 = mrow0 + (lane >> 2);
#pragma unroll
        for (int j = 0; j < 8; j++) {
            int c = nbase + 8 * j + (lane & 3) * 2;
            float bx = __ldg(b2 + c), by = __ldg(b2 + c + 1);
            int gr0 = row0 + r0, gr1 = gr0 + 8;
            if (gr0 < nrows)
                *(__half2*)(Out + (size_t)gr0 * HN + c) =
                    __floats2half2_rn(fmaxf(acc[j][0] + bx, 0.f), fmaxf(acc[j][1] + by, 0.f));
            if (gr1 < nrows)
                *(__half2*)(Out + (size_t)gr1 * HN + c) =
                    __floats2half2_rn(fmaxf(acc[j][2] + bx, 0.f), fmaxf(acc[j][3] + by, 0.f));
        }
    }
}

// ---------------- pooling: fp16 nodes -> fp32 graphs (comp sorted) ----------------
__global__ void k_pool(const __half* __restrict__ h, const int* __restrict__ comp,
                       float* __restrict__ out, int N) {
    int j = threadIdx.x;   // 0..127
    int per = (N + gridDim.x - 1) / gridDim.x;
    int n0 = blockIdx.x * per;
    int n1 = n0 + per; if (n1 > N) n1 = N;
    if (n0 >= n1) return;
    float acc = 0.f;
    int cur = __ldg(comp + n0);
    for (int i = n0; i < n1; i++) {
        int c = __ldg(comp + i);
        if (c != cur) {
            atomicAdd(out + (size_t)cur * HN + j, acc);
            acc = 0.f; cur = c;
        }
        acc += __half2float(__ldg(h + (size_t)i * HN + j));
    }
    atomicAdd(out + (size_t)cur * HN + j, acc);
}

// ---------------- launch ----------------
extern "C" void kernel_launch(void* const* d_in, const int* in_sizes, int n_in,
                              void* d_out, int out_size) {
    const float* x     = (const float*)d_in[0];
    const void*  ei    = d_in[1];
    const void*  n2s   = d_in[2];
    const void*  s2g_i = d_in[3];
    const float* c1W1  = (const float*)d_in[4];
    const float* c1b1  = (const float*)d_in[5];
    const float* c1W2  = (const float*)d_in[6];
    const float* c1b2  = (const float*)d_in[7];
    const float* cW1   = (const float*)d_in[8];
    const float* cb1   = (const float*)d_in[9];
    const float* cW2   = (const float*)d_in[10];
    const float* cb2   = (const float*)d_in[11];

    int N = in_sizes[0];
    int E = in_sizes[1] / 2;
    int G = out_size / HN;

    __half *hA, *hB, *wh;
    float *agg0;
    int *eiX, *comp, *deg, *offs, *cursor, *csr;
    cudaGetSymbolAddress((void**)&hA,     g_hA);
    cudaGetSymbolAddress((void**)&hB,     g_hB);
    cudaGetSymbolAddress((void**)&agg0,   g_agg0);
    cudaGetSymbolAddress((void**)&eiX,    g_ei);
    cudaGetSymbolAddress((void**)&comp,   g_comp);
    cudaGetSymbolAddress((void**)&deg,    g_deg);
    cudaGetSymbolAddress((void**)&offs,   g_offs);
    cudaGetSymbolAddress((void**)&cursor, g_cursor);
    cudaGetSymbolAddress((void**)&csr,    g_csr);
    cudaGetSymbolAddress((void**)&wh,     g_whalf);

    const int SMEM = SMEM_ELEMS * 2;   // 104448 B -> 2 blocks/SM
    cudaFuncSetAttribute(k_layer, cudaFuncAttributeMaxDynamicSharedMemorySize, SMEM);

    // normalize index dtypes (+ fused degree histogram) and composed pool index
    k_detect<<<1, 1>>>((const unsigned long long*)ei);
    k_zeroi<<<(N + 255) / 256, 256>>>(deg, N);
    k_convert_ei<<<(2 * E + 255) / 256, 256>>>(ei, eiX, deg, E);
    k_comp2<<<(N + 255) / 256, 256>>>(n2s, s2g_i, comp, N);

    // convert the 5 weight matrices to fp16 planes
    k_cvtW<<<64, 256>>>(c1W2,          wh + 0 * PLANE);
    k_cvtW<<<64, 256>>>(cW1,           wh + 1 * PLANE);
    k_cvtW<<<64, 256>>>(cW2,           wh + 2 * PLANE);
    k_cvtW<<<64, 256>>>(cW1 + HN * HN, wh + 3 * PLANE);
    k_cvtW<<<64, 256>>>(cW2 + HN * HN, wh + 4 * PLANE);

    // CSR build (dst-major)
    k_scan<<<1, 1024>>>(deg, offs, N);
    k_zeroi<<<(N + 255) / 256, 256>>>(cursor, N);
    k_scatter<<<(E + 255) / 256, 256>>>(eiX, eiX + E, offs, cursor, csr, E);

    int ablocks = (N * 32 + 255) / 256;
    const int LGRID = 296;   // 2 blocks/SM

    // layer 1: scalar agg + fused expansion/MMA -> hB (fp16)
    k_agg0<<<ablocks, 256>>>(offs, csr, x, agg0, N);
    k_layer<<<LGRID, 256, SMEM>>>(nullptr, agg0, c1W1, nullptr, c1b1,
                                  wh + 0 * PLANE, c1b2, hB, N, 0);

    // layers 2..3: fp16 CSR agg + fused dual MMA
    for (int i = 0; i < 2; i++) {
        k_agg_csr<<<ablocks, 256>>>(offs, csr, hB, hA, N);
        k_layer<<<LGRID, 256, SMEM>>>(hA, nullptr, nullptr,
                                      wh + (1 + 2 * i) * PLANE, cb1 + (size_t)i * HN,
                                      wh + (2 + 2 * i) * PLANE, cb2 + (size_t)i * HN,
                                      hB, N, 1);
    }

    // pooling: nodes -> graphs via composed index
    k_zero4<<<((G * HN / 4) + 255) / 256, 256>>>((float*)d_out, G * HN / 4);
    k_pool<<<1024, HN>>>(hB, comp, (float*)d_out, N);
}